// round 11
// baseline (speedup 1.0000x reference)
#include <cuda_runtime.h>
#include <cstdint>
#include <math.h>

// Problem constants
#define VOCAB 50257
#define EMB   16
#define BS    8
#define MCW   512
#define NTOK  (BS * MCW)      // 4096 tokens

// logits GEMM config (3xTF32 mma.sync)
#define KP      48            // split-K: [ah|al|ah] x [bh|bh|bl]
#define KSTEPS  12            // KP / 4 (m16n8k4)
#define NTILE   256           // N per block
#define NBLK_N  197           // ceil(50257/256)
#define PADV    (NBLK_N * NTILE)   // 50432
#define MTILE   128           // M per block
#define NBLK_M  (NTOK / MTILE)     // 32
#define ASTRIDE 52            // smem row pad (floats): (20*grp+k)%32 distinct

// Scratch (device globals: allocation-free)
__device__ float g_Q[NTOK * EMB];
__device__ float g_K[NTOK * EMB];
__device__ float g_V[NTOK * EMB];
__device__ float g_Wt[BS * MCW * MCW];   // g_Wt[b][k][q]
__device__ float g_Ap[NTOK * KP];        // A' rows (tf32 bit patterns as float)
__device__ float g_Bp[PADV * KP];        // B' rows

// ---------------------------------------------------------------------------
// helpers
// ---------------------------------------------------------------------------
__device__ __forceinline__ uint32_t f2tf32(float x) {
    uint32_t u;
    asm("cvt.rna.tf32.f32 %0, %1;" : "=r"(u) : "f"(x));
    return u;
}

__device__ __forceinline__ void mma_tf32_k4(float* c, uint32_t a0, uint32_t a1, uint32_t b0) {
    asm volatile(
        "mma.sync.aligned.m16n8k4.row.col.f32.tf32.tf32.f32 "
        "{%0,%1,%2,%3}, {%4,%5}, {%6}, {%0,%1,%2,%3};"
        : "+f"(c[0]), "+f"(c[1]), "+f"(c[2]), "+f"(c[3])
        : "r"(a0), "r"(a1), "r"(b0));
}

// ---------------------------------------------------------------------------
// Kernel 0: convert Wl into B' = [bh | bh | bl] (tf32), rows >= VOCAB zeroed
// ---------------------------------------------------------------------------
__global__ void prep_b_kernel(const float* __restrict__ Wl) {
    int v = blockIdx.x * 256 + threadIdx.x;
    if (v >= PADV) return;
    float* row = g_Bp + (size_t)v * KP;
    if (v < VOCAB) {
#pragma unroll
        for (int k = 0; k < 16; ++k) {
            float w  = Wl[v * 16 + k];
            float hf = __uint_as_float(f2tf32(w));
            float lf = __uint_as_float(f2tf32(w - hf));
            row[k]      = hf;
            row[16 + k] = hf;
            row[32 + k] = lf;
        }
    } else {
#pragma unroll
        for (int k = 0; k < KP; ++k) row[k] = 0.0f;
    }
}

// ---------------------------------------------------------------------------
// Kernel 1: embedding gather + Q/K/V projections
// ---------------------------------------------------------------------------
__global__ void qkv_kernel(const int* __restrict__ x,
                           const float* __restrict__ emb_table,
                           const float* __restrict__ Wq, const float* __restrict__ bq,
                           const float* __restrict__ Wk, const float* __restrict__ bk,
                           const float* __restrict__ Wv, const float* __restrict__ bv) {
    __shared__ float semb[16][EMB];
    int lt = threadIdx.x >> 4;
    int e  = threadIdx.x & 15;
    int tok = blockIdx.x * 16 + lt;
    int id = x[tok];
    semb[lt][e] = emb_table[id * EMB + e];
    __syncthreads();

    float q = bq[e], k = bk[e], v = bv[e];
#pragma unroll
    for (int j = 0; j < EMB; ++j) {
        float ej = semb[lt][j];
        q = fmaf(Wq[e * EMB + j], ej, q);
        k = fmaf(Wk[e * EMB + j], ej, k);
        v = fmaf(Wv[e * EMB + j], ej, v);
    }
    g_Q[tok * EMB + e] = q;
    g_K[tok * EMB + e] = k;
    g_V[tok * EMB + e] = v;
}

// ---------------------------------------------------------------------------
// Kernel 2: scores + mask + zero->-inf quirk + softmax over QUERY axis
// grid: (MCW/8, BS); block: 512 threads (q). Batched reductions.
// ---------------------------------------------------------------------------
__global__ void attn_weights_kernel() {
    int kc0  = blockIdx.x * 8;
    int b    = blockIdx.y;
    int tid  = threadIdx.x;
    int wid  = tid >> 5;
    int lane = tid & 31;

    __shared__ float sK[8][EMB];
    __shared__ float sredM[16][8];
    __shared__ float sredS[16][8];
    __shared__ float sfinM[8];
    __shared__ float sfinS[8];

    const float4* qrow = reinterpret_cast<const float4*>(g_Q + (b * MCW + tid) * EMB);
    float4 q0 = qrow[0], q1 = qrow[1], q2 = qrow[2], q3 = qrow[3];

    if (tid < 8 * EMB) {
        sK[tid >> 4][tid & 15] = g_K[(b * MCW + kc0 + (tid >> 4)) * EMB + (tid & 15)];
    }
    __syncthreads();

    float val[8];
#pragma unroll
    for (int kc = 0; kc < 8; ++kc) {
        const float* kv = sK[kc];
        float s = 0.0f;
        s = fmaf(q0.x, kv[0],  s); s = fmaf(q0.y, kv[1],  s);
        s = fmaf(q0.z, kv[2],  s); s = fmaf(q0.w, kv[3],  s);
        s = fmaf(q1.x, kv[4],  s); s = fmaf(q1.y, kv[5],  s);
        s = fmaf(q1.z, kv[6],  s); s = fmaf(q1.w, kv[7],  s);
        s = fmaf(q2.x, kv[8],  s); s = fmaf(q2.y, kv[9],  s);
        s = fmaf(q2.z, kv[10], s); s = fmaf(q2.w, kv[11], s);
        s = fmaf(q3.x, kv[12], s); s = fmaf(q3.y, kv[13], s);
        s = fmaf(q3.z, kv[14], s); s = fmaf(q3.w, kv[15], s);
        val[kc] = ((kc0 + kc) <= tid && s != 0.0f) ? s : -INFINITY;
    }

#pragma unroll
    for (int kc = 0; kc < 8; ++kc) {
        float v = val[kc];
#pragma unroll
        for (int o = 16; o > 0; o >>= 1) v = fmaxf(v, __shfl_xor_sync(0xffffffffu, v, o));
        if (lane == 0) sredM[wid][kc] = v;
    }
    __syncthreads();
    if (tid < 8) {
        float m = -INFINITY;
#pragma unroll
        for (int w = 0; w < 16; ++w) m = fmaxf(m, sredM[w][tid]);
        sfinM[tid] = m;
    }
    __syncthreads();

    float p[8];
#pragma unroll
    for (int kc = 0; kc < 8; ++kc) {
        p[kc] = __expf(val[kc] - sfinM[kc]);
        float v = p[kc];
#pragma unroll
        for (int o = 16; o > 0; o >>= 1) v += __shfl_xor_sync(0xffffffffu, v, o);
        if (lane == 0) sredS[wid][kc] = v;
    }
    __syncthreads();
    if (tid < 8) {
        float s = 0.0f;
#pragma unroll
        for (int w = 0; w < 16; ++w) s += sredS[w][tid];
        sfinS[tid] = s;
    }
    __syncthreads();

#pragma unroll
    for (int kc = 0; kc < 8; ++kc) {
        float w = p[kc] / sfinS[kc];
        g_Wt[((size_t)(b * MCW + kc0 + kc)) * MCW + tid] = w;
    }
}

// ---------------------------------------------------------------------------
// Kernel 3: out = weights @ V, written directly as A' = [ah | al | ah] (tf32)
// ---------------------------------------------------------------------------
__global__ void attn_out_kernel() {
    int b  = blockIdx.y;
    int w  = blockIdx.x * 16 + (threadIdx.x & 15);
    int e  = threadIdx.x >> 4;

    __shared__ float sV[MCW * EMB];
    const float* Vb = g_V + b * MCW * EMB;
    for (int i = threadIdx.x; i < MCW * EMB; i += 256) sV[i] = Vb[i];
    __syncthreads();

    const float* Wtb = g_Wt + (size_t)b * MCW * MCW;
    float acc = 0.0f;
#pragma unroll 8
    for (int p = 0; p < MCW; ++p)
        acc = fmaf(Wtb[p * MCW + w], sV[p * EMB + e], acc);

    int tok = b * MCW + w;
    float hf = __uint_as_float(f2tf32(acc));
    float lf = __uint_as_float(f2tf32(acc - hf));
    g_Ap[tok * KP + e]      = hf;
    g_Ap[tok * KP + 16 + e] = lf;
    g_Ap[tok * KP + 32 + e] = hf;
}

// ---------------------------------------------------------------------------
// Kernel 4: logits GEMM on tensor cores (mma.sync m16n8k4 tf32, 3x split)
// grid: (32 M-blocks, 197 N-blocks); block: 256 thr = 8 warps.
// Block tile: M=128 (A' in smem, pad-52), N=256 (warp owns 32 cols; its 48
// B-fragment regs loaded once from g_Bp). Bias added in epilogue.
// ---------------------------------------------------------------------------
__global__ void __launch_bounds__(256)
logits_mma_kernel(const float* __restrict__ bl, float* __restrict__ logits) {
    __shared__ float sA[MTILE * ASTRIDE];   // 26624 B

    int tid  = threadIdx.x;
    int warp = tid >> 5;
    int lane = tid & 31;
    int grp  = lane >> 2;     // 0..7
    int tidg = lane & 3;      // 0..3

    int mbase = blockIdx.x * MTILE;
    int nwarp = blockIdx.y * NTILE + warp * 32;   // this warp's N base

    // --- load B fragments: breg[ks][nt] = B'[n = nwarp+nt*8+grp][k = ks*4+tidg]
    uint32_t breg[KSTEPS][4];
#pragma unroll
    for (int ks = 0; ks < KSTEPS; ++ks) {
#pragma unroll
        for (int nt = 0; nt < 4; ++nt) {
            breg[ks][nt] = __float_as_uint(
                g_Bp[(size_t)(nwarp + nt * 8 + grp) * KP + ks * 4 + tidg]);
        }
    }

    // --- stage A' tile (128 rows x 48 floats) into padded smem
    for (int i = tid; i < MTILE * 12; i += 256) {
        int row = i / 12;
        int c4  = i % 12;
        float4 v = *reinterpret_cast<const float4*>(&g_Ap[(size_t)(mbase + row) * KP + c4 * 4]);
        *reinterpret_cast<float4*>(&sA[row * ASTRIDE + c4 * 4]) = v;
    }
    __syncthreads();

    // --- 8 m-subtiles of 16 rows
#pragma unroll 1
    for (int msub = 0; msub < MTILE / 16; ++msub) {
        float c[4][4] = {{0.f,0.f,0.f,0.f},{0.f,0.f,0.f,0.f},
                         {0.f,0.f,0.f,0.f},{0.f,0.f,0.f,0.f}};
        int arow = msub * 16 + grp;
#pragma unroll
        for (int ks = 0; ks < KSTEPS; ++ks) {
            uint32_t a0 = __float_as_uint(sA[arow * ASTRIDE + ks * 4 + tidg]);
            uint32_t a1 = __float_as_uint(sA[(arow + 8) * ASTRIDE + ks * 4 + tidg]);
            mma_tf32_k4(c[0], a0, a1, breg[ks][0]);
            mma_tf32_k4(c[1], a0, a1, breg[ks][1]);
            mma_tf32_k4(c[2], a0, a1, breg[ks][2]);
            mma_tf32_k4(c[3], a0, a1, breg[ks][3]);
        }

        // epilogue: bias + store.  c0/c1: row=grp, cols 2*tidg,2*tidg+1;
        //                          c2/c3: row=grp+8, same cols.
        int row0 = mbase + msub * 16 + grp;
        size_t rb0 = (size_t)row0 * VOCAB;
        size_t rb1 = rb0 + (size_t)8 * VOCAB;
#pragma unroll
        for (int nt = 0; nt < 4; ++nt) {
            int col0 = nwarp + nt * 8 + 2 * tidg;
            if (col0 < VOCAB) {
                float b = bl[col0];
                logits[rb0 + col0] = c[nt][0] + b;
                logits[rb1 + col0] = c[nt][2] + b;
            }
            if (col0 + 1 < VOCAB) {
                float b = bl[col0 + 1];
                logits[rb0 + col0 + 1] = c[nt][1] + b;
                logits[rb1 + col0 + 1] = c[nt][3] + b;
            }
        }
    }
}

// ---------------------------------------------------------------------------
extern "C" void kernel_launch(void* const* d_in, const int* in_sizes, int n_in,
                              void* d_out, int out_size) {
    const int*   x         = (const int*)  d_in[0];
    const float* emb_table = (const float*)d_in[1];
    const float* Wq        = (const float*)d_in[2];
    const float* bq        = (const float*)d_in[3];
    const float* Wk        = (const float*)d_in[4];
    const float* bk        = (const float*)d_in[5];
    const float* Wv        = (const float*)d_in[6];
    const float* bv        = (const float*)d_in[7];
    const float* Wl        = (const float*)d_in[8];
    const float* bl        = (const float*)d_in[9];
    float* logits          = (float*)d_out;

    prep_b_kernel<<<(PADV + 255) / 256, 256>>>(Wl);

    qkv_kernel<<<NTOK / 16, 256>>>(x, emb_table, Wq, bq, Wk, bk, Wv, bv);

    dim3 g2(MCW / 8, BS);
    attn_weights_kernel<<<g2, MCW>>>();

    dim3 g3(MCW / 16, BS);
    attn_out_kernel<<<g3, 256>>>();

    dim3 g4(NBLK_M, NBLK_N);
    logits_mma_kernel<<<g4, 256>>>(bl, logits);
}

// round 12
// speedup vs baseline: 1.3244x; 1.3244x over previous
#include <cuda_runtime.h>
#include <cstdint>
#include <math.h>

// Problem constants
#define VOCAB 50257
#define EMB   16
#define BS    8
#define MCW   512
#define NTOK  (BS * MCW)      // 4096 tokens

// logits GEMM config (3xTF32 mma.sync, m16n8k8)
#define KP      48            // split-K: [ah|al|ah] x [bh|bh|bl]
#define KSTEPS  6             // KP / 8
#define NTILE   256           // N per block
#define NBLK_N  197           // ceil(50257/256)
#define PADV    (NBLK_N * NTILE)   // 50432
#define MTILE   128           // M per block
#define NBLK_M  (NTOK / MTILE)     // 32
#define ASTRIDE 52            // smem row pad (floats) -> conflict-free frag reads

// Scratch (device globals: allocation-free)
__device__ float g_Q[NTOK * EMB];
__device__ float g_K[NTOK * EMB];
__device__ float g_V[NTOK * EMB];
__device__ float g_Wt[BS * MCW * MCW];   // g_Wt[b][k][q]
__device__ float g_Ap[NTOK * KP];        // A' rows (tf32 bit patterns)
__device__ float2 g_Bf[PADV * 24];       // B fragments: [(n/8)*6+ks]*32 + lane

// ---------------------------------------------------------------------------
__device__ __forceinline__ uint32_t f2tf32(float x) {
    uint32_t u;
    asm("cvt.rna.tf32.f32 %0, %1;" : "=r"(u) : "f"(x));
    return u;
}

__device__ __forceinline__ void mma_tf32_k8(float* c,
                                            uint32_t a0, uint32_t a1, uint32_t a2, uint32_t a3,
                                            uint32_t b0, uint32_t b1) {
    asm volatile(
        "mma.sync.aligned.m16n8k8.row.col.f32.tf32.tf32.f32 "
        "{%0,%1,%2,%3}, {%4,%5,%6,%7}, {%8,%9}, {%0,%1,%2,%3};"
        : "+f"(c[0]), "+f"(c[1]), "+f"(c[2]), "+f"(c[3])
        : "r"(a0), "r"(a1), "r"(a2), "r"(a3), "r"(b0), "r"(b1));
}

// ---------------------------------------------------------------------------
// Kernel 0: build fragment-ready B table.
// B'[v][k]: k<16 -> bh[k]; k<32 -> bh[k-16]; k>=32 -> bl[k-32].
// g_Bf[((v>>3)*6 + ks)*32 + (v&7)*4 + tidg] = (B'[v][8ks+tidg], B'[v][8ks+tidg+4])
// -> in the GEMM, lane L loads element L: fully coalesced 256B per fragment.
// ---------------------------------------------------------------------------
__global__ void prep_b_kernel(const float* __restrict__ Wl) {
    int v = blockIdx.x * 256 + threadIdx.x;
    if (v >= PADV) return;

    float bh[16], blo[16];
    if (v < VOCAB) {
#pragma unroll
        for (int k = 0; k < 16; ++k) {
            float w  = Wl[v * 16 + k];
            float hf = __uint_as_float(f2tf32(w));
            bh[k]  = hf;
            blo[k] = __uint_as_float(f2tf32(w - hf));
        }
    } else {
#pragma unroll
        for (int k = 0; k < 16; ++k) { bh[k] = 0.0f; blo[k] = 0.0f; }
    }

    size_t base = (size_t)(v >> 3) * 6 * 32 + (size_t)(v & 7) * 4;
#pragma unroll
    for (int ks = 0; ks < 6; ++ks) {
#pragma unroll
        for (int tg = 0; tg < 4; ++tg) {
            int k1 = 8 * ks + tg;
            int k2 = k1 + 4;
            float f1 = (k1 < 16) ? bh[k1] : (k1 < 32) ? bh[k1 - 16] : blo[k1 - 32];
            float f2 = (k2 < 16) ? bh[k2] : (k2 < 32) ? bh[k2 - 16] : blo[k2 - 32];
            g_Bf[base + (size_t)ks * 32 + tg] = make_float2(f1, f2);
        }
    }
}

// ---------------------------------------------------------------------------
// Kernel 1: embedding gather + Q/K/V projections
// ---------------------------------------------------------------------------
__global__ void qkv_kernel(const int* __restrict__ x,
                           const float* __restrict__ emb_table,
                           const float* __restrict__ Wq, const float* __restrict__ bq,
                           const float* __restrict__ Wk, const float* __restrict__ bk,
                           const float* __restrict__ Wv, const float* __restrict__ bv) {
    __shared__ float semb[16][EMB];
    int lt = threadIdx.x >> 4;
    int e  = threadIdx.x & 15;
    int tok = blockIdx.x * 16 + lt;
    int id = x[tok];
    semb[lt][e] = emb_table[id * EMB + e];
    __syncthreads();

    float q = bq[e], k = bk[e], v = bv[e];
#pragma unroll
    for (int j = 0; j < EMB; ++j) {
        float ej = semb[lt][j];
        q = fmaf(Wq[e * EMB + j], ej, q);
        k = fmaf(Wk[e * EMB + j], ej, k);
        v = fmaf(Wv[e * EMB + j], ej, v);
    }
    g_Q[tok * EMB + e] = q;
    g_K[tok * EMB + e] = k;
    g_V[tok * EMB + e] = v;
}

// ---------------------------------------------------------------------------
// Kernel 2: scores + mask + zero->-inf quirk + softmax over QUERY axis
// ---------------------------------------------------------------------------
__global__ void attn_weights_kernel() {
    int kc0  = blockIdx.x * 8;
    int b    = blockIdx.y;
    int tid  = threadIdx.x;
    int wid  = tid >> 5;
    int lane = tid & 31;

    __shared__ float sK[8][EMB];
    __shared__ float sredM[16][8];
    __shared__ float sredS[16][8];
    __shared__ float sfinM[8];
    __shared__ float sfinS[8];

    const float4* qrow = reinterpret_cast<const float4*>(g_Q + (b * MCW + tid) * EMB);
    float4 q0 = qrow[0], q1 = qrow[1], q2 = qrow[2], q3 = qrow[3];

    if (tid < 8 * EMB) {
        sK[tid >> 4][tid & 15] = g_K[(b * MCW + kc0 + (tid >> 4)) * EMB + (tid & 15)];
    }
    __syncthreads();

    float val[8];
#pragma unroll
    for (int kc = 0; kc < 8; ++kc) {
        const float* kv = sK[kc];
        float s = 0.0f;
        s = fmaf(q0.x, kv[0],  s); s = fmaf(q0.y, kv[1],  s);
        s = fmaf(q0.z, kv[2],  s); s = fmaf(q0.w, kv[3],  s);
        s = fmaf(q1.x, kv[4],  s); s = fmaf(q1.y, kv[5],  s);
        s = fmaf(q1.z, kv[6],  s); s = fmaf(q1.w, kv[7],  s);
        s = fmaf(q2.x, kv[8],  s); s = fmaf(q2.y, kv[9],  s);
        s = fmaf(q2.z, kv[10], s); s = fmaf(q2.w, kv[11], s);
        s = fmaf(q3.x, kv[12], s); s = fmaf(q3.y, kv[13], s);
        s = fmaf(q3.z, kv[14], s); s = fmaf(q3.w, kv[15], s);
        val[kc] = ((kc0 + kc) <= tid && s != 0.0f) ? s : -INFINITY;
    }

#pragma unroll
    for (int kc = 0; kc < 8; ++kc) {
        float v = val[kc];
#pragma unroll
        for (int o = 16; o > 0; o >>= 1) v = fmaxf(v, __shfl_xor_sync(0xffffffffu, v, o));
        if (lane == 0) sredM[wid][kc] = v;
    }
    __syncthreads();
    if (tid < 8) {
        float m = -INFINITY;
#pragma unroll
        for (int w = 0; w < 16; ++w) m = fmaxf(m, sredM[w][tid]);
        sfinM[tid] = m;
    }
    __syncthreads();

    float p[8];
#pragma unroll
    for (int kc = 0; kc < 8; ++kc) {
        p[kc] = __expf(val[kc] - sfinM[kc]);
        float v = p[kc];
#pragma unroll
        for (int o = 16; o > 0; o >>= 1) v += __shfl_xor_sync(0xffffffffu, v, o);
        if (lane == 0) sredS[wid][kc] = v;
    }
    __syncthreads();
    if (tid < 8) {
        float s = 0.0f;
#pragma unroll
        for (int w = 0; w < 16; ++w) s += sredS[w][tid];
        sfinS[tid] = s;
    }
    __syncthreads();

#pragma unroll
    for (int kc = 0; kc < 8; ++kc) {
        float w = p[kc] / sfinS[kc];
        g_Wt[((size_t)(b * MCW + kc0 + kc)) * MCW + tid] = w;
    }
}

// ---------------------------------------------------------------------------
// Kernel 3: out = weights @ V, written directly as A' = [ah | al | ah] (tf32)
// ---------------------------------------------------------------------------
__global__ void attn_out_kernel() {
    int b  = blockIdx.y;
    int w  = blockIdx.x * 16 + (threadIdx.x & 15);
    int e  = threadIdx.x >> 4;

    __shared__ float sV[MCW * EMB];
    const float* Vb = g_V + b * MCW * EMB;
    for (int i = threadIdx.x; i < MCW * EMB; i += 256) sV[i] = Vb[i];
    __syncthreads();

    const float* Wtb = g_Wt + (size_t)b * MCW * MCW;
    float acc = 0.0f;
#pragma unroll 8
    for (int p = 0; p < MCW; ++p)
        acc = fmaf(Wtb[p * MCW + w], sV[p * EMB + e], acc);

    int tok = b * MCW + w;
    float hf = __uint_as_float(f2tf32(acc));
    float lf = __uint_as_float(f2tf32(acc - hf));
    g_Ap[tok * KP + e]      = hf;
    g_Ap[tok * KP + 16 + e] = lf;
    g_Ap[tok * KP + 32 + e] = hf;
}

// ---------------------------------------------------------------------------
// Kernel 4: logits GEMM (mma.sync m16n8k8 tf32, 3x split)
// grid: (32 M-blocks, 197 N-blocks); block: 256 thr = 8 warps.
// B fragments: coalesced float2 loads from g_Bf (24 per warp nt-block).
// A' tile in pad-52 smem; bias in regs, reused across 8 m-subtiles.
// ---------------------------------------------------------------------------
__global__ void __launch_bounds__(256)
logits_mma_kernel(const float* __restrict__ bl, float* __restrict__ logits) {
    __shared__ float sA[MTILE * ASTRIDE];   // 26624 B

    int tid  = threadIdx.x;
    int warp = tid >> 5;
    int lane = tid & 31;
    int grp  = lane >> 2;     // 0..7
    int tidg = lane & 3;      // 0..3

    int mbase = blockIdx.x * MTILE;
    int nwarp = blockIdx.y * NTILE + warp * 32;

    // --- B fragments: coalesced (lane L -> element L)
    float2 breg[4][KSTEPS];
#pragma unroll
    for (int nt = 0; nt < 4; ++nt) {
        size_t nb = (size_t)((nwarp >> 3) + nt) * 6 * 32;
#pragma unroll
        for (int ks = 0; ks < KSTEPS; ++ks)
            breg[nt][ks] = g_Bf[nb + (size_t)ks * 32 + lane];
    }

    // --- bias (cols shared by both row halves; col0 even -> aligned float2)
    float2 biasv[4];
#pragma unroll
    for (int nt = 0; nt < 4; ++nt) {
        int c0 = nwarp + nt * 8 + 2 * tidg;
        if (c0 + 1 < VOCAB)      biasv[nt] = *reinterpret_cast<const float2*>(bl + c0);
        else if (c0 < VOCAB)     biasv[nt] = make_float2(bl[c0], 0.0f);
        else                     biasv[nt] = make_float2(0.0f, 0.0f);
    }

    // --- stage A' tile (128 rows x 48 floats) into padded smem
    for (int i = tid; i < MTILE * 12; i += 256) {
        int row = i / 12;
        int c4  = i % 12;
        float4 v = *reinterpret_cast<const float4*>(&g_Ap[(size_t)(mbase + row) * KP + c4 * 4]);
        *reinterpret_cast<float4*>(&sA[row * ASTRIDE + c4 * 4]) = v;
    }
    __syncthreads();

#pragma unroll 1
    for (int msub = 0; msub < MTILE / 16; ++msub) {
        float c[4][4] = {{0.f,0.f,0.f,0.f},{0.f,0.f,0.f,0.f},
                         {0.f,0.f,0.f,0.f},{0.f,0.f,0.f,0.f}};
        int ar = msub * 16 + grp;
#pragma unroll
        for (int ks = 0; ks < KSTEPS; ++ks) {
            int kb = ks * 8 + tidg;
            uint32_t a0 = __float_as_uint(sA[ar * ASTRIDE + kb]);
            uint32_t a1 = __float_as_uint(sA[(ar + 8) * ASTRIDE + kb]);
            uint32_t a2 = __float_as_uint(sA[ar * ASTRIDE + kb + 4]);
            uint32_t a3 = __float_as_uint(sA[(ar + 8) * ASTRIDE + kb + 4]);
#pragma unroll
            for (int nt = 0; nt < 4; ++nt) {
                mma_tf32_k8(c[nt], a0, a1, a2, a3,
                            __float_as_uint(breg[nt][ks].x),
                            __float_as_uint(breg[nt][ks].y));
            }
        }

        int row0 = mbase + msub * 16 + grp;
        size_t rb0 = (size_t)row0 * VOCAB;
        size_t rb1 = rb0 + (size_t)8 * VOCAB;
#pragma unroll
        for (int nt = 0; nt < 4; ++nt) {
            int col0 = nwarp + nt * 8 + 2 * tidg;
            if (col0 < VOCAB) {
                logits[rb0 + col0] = c[nt][0] + biasv[nt].x;
                logits[rb1 + col0] = c[nt][2] + biasv[nt].x;
            }
            if (col0 + 1 < VOCAB) {
                logits[rb0 + col0 + 1] = c[nt][1] + biasv[nt].y;
                logits[rb1 + col0 + 1] = c[nt][3] + biasv[nt].y;
            }
        }
    }
}

// ---------------------------------------------------------------------------
extern "C" void kernel_launch(void* const* d_in, const int* in_sizes, int n_in,
                              void* d_out, int out_size) {
    const int*   x         = (const int*)  d_in[0];
    const float* emb_table = (const float*)d_in[1];
    const float* Wq        = (const float*)d_in[2];
    const float* bq        = (const float*)d_in[3];
    const float* Wk        = (const float*)d_in[4];
    const float* bk        = (const float*)d_in[5];
    const float* Wv        = (const float*)d_in[6];
    const float* bv        = (const float*)d_in[7];
    const float* Wl        = (const float*)d_in[8];
    const float* bl        = (const float*)d_in[9];
    float* logits          = (float*)d_out;

    prep_b_kernel<<<(PADV + 255) / 256, 256>>>(Wl);

    qkv_kernel<<<NTOK / 16, 256>>>(x, emb_table, Wq, bq, Wk, bk, Wv, bv);

    dim3 g2(MCW / 8, BS);
    attn_weights_kernel<<<g2, MCW>>>();

    dim3 g3(MCW / 16, BS);
    attn_out_kernel<<<g3, 256>>>();

    dim3 g4(NBLK_M, NBLK_N);
    logits_mma_kernel<<<g4, 256>>>(bl, logits);
}